// round 9
// baseline (speedup 1.0000x reference)
#include <cuda_runtime.h>

#define BB 8
#define NN 20000
#define DD 640
#define RR 2500
#define BINS 10
#define HID 128
#define EPSV 1e-5f
#define NB 592              // persistent grid: 4 blocks/SM on 148 SMs
#define NWARPS (NB * 4)

typedef unsigned long long ull;

// ---------------- scratch (zero-init at load; g_pooled fully overwritten) ----
__device__ float g_pooled[RR * BB * BINS];   // [r][b][bin] segment sums
__device__ int   g_off[RR + 1];              // segment offsets (res_id sorted)
__device__ float g_sum[HID];
__device__ float g_sumsq[HID];
__device__ unsigned int g_done;              // phase-1 barrier
__device__ unsigned int g_done2;             // end counter (no spinners)

// ---------------- packed f32x2 helpers (sm_100+) ----------------
__device__ __forceinline__ ull pk2(float lo, float hi) {
    ull r; asm("mov.b64 %0,{%1,%2};" : "=l"(r) : "f"(lo), "f"(hi)); return r;
}
__device__ __forceinline__ void upk2(ull v, float& lo, float& hi) {
    asm("mov.b64 {%0,%1},%2;" : "=f"(lo), "=f"(hi) : "l"(v));
}
__device__ __forceinline__ ull add2(ull a, ull b) {
    ull d; asm("add.rn.f32x2 %0,%1,%2;" : "=l"(d) : "l"(a), "l"(b)); return d;
}
__device__ __forceinline__ ull mul2(ull a, ull b) {
    ull d; asm("mul.rn.f32x2 %0,%1,%2;" : "=l"(d) : "l"(a), "l"(b)); return d;
}
__device__ __forceinline__ ull fma2(ull a, ull b, ull c) {
    ull d; asm("fma.rn.f32x2 %0,%1,%2,%3;" : "=l"(d) : "l"(a), "l"(b), "l"(c)); return d;
}
__device__ __forceinline__ ull relu2(ull a) {
    float lo, hi; upk2(a, lo, hi);
    return pk2(fmaxf(lo, 0.0f), fmaxf(hi, 0.0f));
}

// ---------------- K1: atomic-free pooling (reads all 410MB of x) ----------------
// One block per residue, one warp per batch. Each warp reads its contiguous
// segment rows (cnt x 160 float4, coalesced), accumulates 5 bins per lane-half,
// reduces once, and STORES the 10 bins (full overwrite -> no zeroing needed).
// Thread 0/32 binary-search the segment bounds and publish g_off for k_fused.
__global__ void __launch_bounds__(256) k_pool(const float4* __restrict__ x4,
                                              const int* __restrict__ res_id) {
    int r = blockIdx.x;
    __shared__ int s_o0, s_o1;
    if (threadIdx.x == 0) {
        int lo = 0, hi = NN;                       // lower_bound(r)
        while (lo < hi) { int m = (lo + hi) >> 1; if (res_id[m] < r) lo = m + 1; else hi = m; }
        s_o0 = lo;
        g_off[r] = lo;
        if (r == 0) g_off[RR] = NN;
    }
    if (threadIdx.x == 32) {
        int lo = 0, hi = NN;                       // lower_bound(r+1)
        while (lo < hi) { int m = (lo + hi) >> 1; if (res_id[m] < r + 1) lo = m + 1; else hi = m; }
        s_o1 = lo;
    }
    __syncthreads();
    int o0 = s_o0, o1 = s_o1;
    int b = threadIdx.x >> 5;
    int lane = threadIdx.x & 31;

    float s[5] = {0, 0, 0, 0, 0};
    for (int n = o0; n < o1; n++) {
        const float4* row = x4 + ((size_t)b * NN + n) * (DD / 4);
#pragma unroll
        for (int k = 0; k < 5; k++) {
            float4 v = __ldcs(&row[lane + 32 * k]);   // read-once: evict-first
            s[k] += (v.x + v.y) + (v.z + v.w);
        }
    }
#pragma unroll
    for (int k = 0; k < 5; k++) {
#pragma unroll
        for (int off = 8; off >= 1; off >>= 1)
            s[k] += __shfl_down_sync(0xffffffffu, s[k], off, 16);
    }
    if ((lane & 15) == 0) {
        int half = lane >> 4;
        float* dst = &g_pooled[((size_t)r * BB + b) * BINS];
#pragma unroll
        for (int k = 0; k < 5; k++)
            dst[2 * k + half] = s[k];                 // plain store, no atomic
    }
}

// Per-residue a2[b][k2] using smem-resident packed W1; warp handles [lo,hi)
// (its half of the residue's atom range).
#define COMPUTE_A2_SMEM()                                                       \
    int o0 = g_off[r], o1 = g_off[r + 1], cnt = o1 - o0;                        \
    int lo = o0 + ((cnt * half) >> 1), hi = o0 + ((cnt * (half + 1)) >> 1);     \
    int subcnt = hi - lo;                                                       \
    float inv = 1.0f / ((float)cnt * 64.0f);                                    \
    const float* pp = &g_pooled[(size_t)r * BB * BINS];                         \
    float p0 = pp[lane], p1 = pp[lane + 32], p2 = (lane < 16) ? pp[lane + 64] : 0.0f; \
    ull a2[BB][2];                                                              \
    _Pragma("unroll")                                                           \
    for (int b = 0; b < BB; b++) { a2[b][0] = bb2[0]; a2[b][1] = bb2[1]; }      \
    _Pragma("unroll")                                                           \
    for (int j = 0; j < BINS; j++) {                                            \
        ull wj0 = s_w1p[j][0][lane], wj1 = s_w1p[j][1][lane];                   \
        _Pragma("unroll")                                                       \
        for (int b = 0; b < BB; b++) {                                          \
            int idx = b * BINS + j;                                             \
            float v = __shfl_sync(0xffffffffu, idx < 32 ? p0 : (idx < 64 ? p1 : p2), idx & 31); \
            float pm = v * inv;                                                 \
            ull pm2 = pk2(pm, pm);                                              \
            a2[b][0] = fma2(pm2, wj0, a2[b][0]);                                \
            a2[b][1] = fma2(pm2, wj1, a2[b][1]);                                \
        }                                                                       \
    }

// ---------------- K2: persistent fused stats + fold + output -----------------
__global__ void __launch_bounds__(128, 4) k_fused(
        const float* __restrict__ cond, const float* __restrict__ W1,
        const float* __restrict__ b1, const float* __restrict__ gamma,
        const float* __restrict__ beta, const float* __restrict__ W2,
        const float* __restrict__ b2, float* __restrict__ out) {
    __shared__ ull s_w1p[BINS][2][32];   // packed pooled-part of W1 (5KB)
    __shared__ float ssum[HID];
    __shared__ float ssq[HID];
    __shared__ bool s_last;
    int t = threadIdx.x, lane = t & 31;

    // cooperative pack of W1[0:10] into smem
    for (int e = t; e < BINS * 64; e += 128) {
        int j = e >> 6, k2 = (e >> 5) & 1, l = e & 31;
        int f = l + 64 * k2;
        s_w1p[j][k2][l] = pk2(__ldg(&W1[j * HID + f]), __ldg(&W1[j * HID + f + 32]));
    }
    ssum[t] = 0.0f; ssq[t] = 0.0f;

    // conditioner part + bias in registers (feature pairing (f, f+32))
    ull w1c2[3][2], bb2[2];
#pragma unroll
    for (int j = 0; j < 3; j++) {
        w1c2[j][0] = pk2(__ldg(&W1[(BINS + j) * HID + lane]), __ldg(&W1[(BINS + j) * HID + lane + 32]));
        w1c2[j][1] = pk2(__ldg(&W1[(BINS + j) * HID + lane + 64]), __ldg(&W1[(BINS + j) * HID + lane + 96]));
    }
    bb2[0] = pk2(__ldg(&b1[lane]), __ldg(&b1[lane + 32]));
    bb2[1] = pk2(__ldg(&b1[lane + 64]), __ldg(&b1[lane + 96]));
    __syncthreads();

    int warp0 = (blockIdx.x * blockDim.x + t) >> 5;

    // ================= phase 1: stats =================
    ull ls2[2] = {0, 0}, lq2[2] = {0, 0};
    for (int task = warp0; task < 2 * RR; task += NWARPS) {
        int r = task >> 1, half = task & 1;
        COMPUTE_A2_SMEM();
        float cseg = (lane < 3 * subcnt) ? __ldg(&cond[lo * 3 + lane]) : 0.0f;
        for (int i = 0; i < subcnt; i++) {
            float c0 = __shfl_sync(0xffffffffu, cseg, 3 * i);
            float c1 = __shfl_sync(0xffffffffu, cseg, 3 * i + 1);
            float c2 = __shfl_sync(0xffffffffu, cseg, 3 * i + 2);
            ull c02 = pk2(c0, c0), c12 = pk2(c1, c1), c22 = pk2(c2, c2);
#pragma unroll
            for (int k2 = 0; k2 < 2; k2++) {
                ull cc = fma2(c02, w1c2[0][k2], fma2(c12, w1c2[1][k2], mul2(c22, w1c2[2][k2])));
#pragma unroll
                for (int b = 0; b < BB; b++) {
                    ull v = relu2(add2(a2[b][k2], cc));
                    ls2[k2] = add2(ls2[k2], v);
                    lq2[k2] = fma2(v, v, lq2[k2]);
                }
            }
        }
    }
    {
        float x0, x1;
        upk2(ls2[0], x0, x1); atomicAdd(&ssum[lane], x0); atomicAdd(&ssum[lane + 32], x1);
        upk2(ls2[1], x0, x1); atomicAdd(&ssum[lane + 64], x0); atomicAdd(&ssum[lane + 96], x1);
        upk2(lq2[0], x0, x1); atomicAdd(&ssq[lane], x0);  atomicAdd(&ssq[lane + 32], x1);
        upk2(lq2[1], x0, x1); atomicAdd(&ssq[lane + 64], x0); atomicAdd(&ssq[lane + 96], x1);
    }
    __syncthreads();
    atomicAdd(&g_sum[t], ssum[t]);
    atomicAdd(&g_sumsq[t], ssq[t]);
    __syncthreads();

    // ================= phase barrier (all blocks resident by construction) ====
    __threadfence();
    if (t == 0) {
        atomicAdd(&g_done, 1u);
        while (atomicAdd(&g_done, 0u) < (unsigned)gridDim.x) __nanosleep(64);
    }
    __syncthreads();
    __threadfence();

    // ================= per-warp layernorm fold =================
    ull w22[2][3];
    float bo0, bo1, bo2;
    {
        const float invn = 1.0f / (float)(BB * NN);
        float w2s[4][3];
        float offc[3] = {0, 0, 0};
#pragma unroll
        for (int k = 0; k < 4; k++) {
            int f = lane + 32 * k;
            float mu = g_sum[f] * invn;
            float var = g_sumsq[f] * invn - mu * mu;
            float s = rsqrtf(var + EPSV) * __ldg(&gamma[f]);
            float off = __ldg(&beta[f]) - mu * s;
#pragma unroll
            for (int j = 0; j < 3; j++) {
                float w = __ldg(&W2[f * 3 + j]);
                w2s[k][j] = w * s;
                offc[j] += off * w;
            }
        }
#pragma unroll
        for (int o = 16; o >= 1; o >>= 1) {
            offc[0] += __shfl_xor_sync(0xffffffffu, offc[0], o);
            offc[1] += __shfl_xor_sync(0xffffffffu, offc[1], o);
            offc[2] += __shfl_xor_sync(0xffffffffu, offc[2], o);
        }
        bo0 = offc[0] + __ldg(&b2[0]);
        bo1 = offc[1] + __ldg(&b2[1]);
        bo2 = offc[2] + __ldg(&b2[2]);
#pragma unroll
        for (int j = 0; j < 3; j++) {
            w22[0][j] = pk2(w2s[0][j], w2s[1][j]);
            w22[1][j] = pk2(w2s[2][j], w2s[3][j]);
        }
    }

    // ================= phase 2: output =================
    for (int task = warp0; task < 2 * RR; task += NWARPS) {
        int r = task >> 1, half = task & 1;
        COMPUTE_A2_SMEM();
        float cseg = (lane < 3 * subcnt) ? __ldg(&cond[lo * 3 + lane]) : 0.0f;

        for (int i = 0; i < subcnt; i++) {
            float c0 = __shfl_sync(0xffffffffu, cseg, 3 * i);
            float c1 = __shfl_sync(0xffffffffu, cseg, 3 * i + 1);
            float c2 = __shfl_sync(0xffffffffu, cseg, 3 * i + 2);
            ull c02 = pk2(c0, c0), c12 = pk2(c1, c1), c22 = pk2(c2, c2);
            ull cc[2];
#pragma unroll
            for (int k2 = 0; k2 < 2; k2++)
                cc[k2] = fma2(c02, w1c2[0][k2], fma2(c12, w1c2[1][k2], mul2(c22, w1c2[2][k2])));

#pragma unroll
            for (int g = 0; g < 2; g++) {
                ull y01[4];
                ull y2p[2];
#pragma unroll
                for (int q = 0; q < 4; q++) {
                    int b = g * 4 + q;
                    ull s0 = 0, s1 = 0, s2 = 0;
#pragma unroll
                    for (int k2 = 0; k2 < 2; k2++) {
                        ull v = relu2(add2(a2[b][k2], cc[k2]));
                        s0 = fma2(v, w22[k2][0], s0);
                        s1 = fma2(v, w22[k2][1], s1);
                        s2 = fma2(v, w22[k2][2], s2);
                    }
                    float u0, u1, r0, r1, r2;
                    upk2(s0, u0, u1); r0 = u0 + u1;
                    upk2(s1, u0, u1); r1 = u0 + u1;
                    upk2(s2, u0, u1); r2 = u0 + u1;
                    y01[q] = pk2(r0, r1);
                    if (q & 1) {
                        float plo, phi; upk2(y2p[q >> 1], plo, phi);
                        y2p[q >> 1] = pk2(plo, r2);
                    } else {
                        y2p[q >> 1] = pk2(r2, 0.0f);
                    }
                }
#pragma unroll
                for (int o = 16; o >= 1; o >>= 1) {
#pragma unroll
                    for (int q = 0; q < 4; q++)
                        y01[q] = add2(y01[q], __shfl_down_sync(0xffffffffu, y01[q], o));
#pragma unroll
                    for (int q = 0; q < 2; q++)
                        y2p[q] = add2(y2p[q], __shfl_down_sync(0xffffffffu, y2p[q], o));
                }
                if (lane == 0) {
#pragma unroll
                    for (int q = 0; q < 4; q++) {
                        int b = g * 4 + q;
                        float r0, r1, r2, rlo, rhi;
                        upk2(y01[q], r0, r1);
                        upk2(y2p[q >> 1], rlo, rhi);
                        r2 = (q & 1) ? rhi : rlo;
                        float* p = out + ((size_t)b * NN + (lo + i)) * 3;
                        p[0] = r0 + bo0;
                        p[1] = r1 + bo1;
                        p[2] = r2 + bo2;
                    }
                }
            }
        }
    }

    // ================= cleanup: last block resets tiny state (no spin) ========
    // Every block passed the g_done spin before arriving here, so resetting
    // g_done/g_sum is race-free once ALL blocks have incremented g_done2.
    __syncthreads();
    __threadfence();
    if (t == 0) s_last = (atomicAdd(&g_done2, 1u) == (unsigned)gridDim.x - 1);
    __syncthreads();
    if (s_last) {
        g_sum[t] = 0.0f;
        g_sumsq[t] = 0.0f;
        __syncthreads();
        __threadfence();
        if (t == 0) { g_done = 0; g_done2 = 0; }
    }
}

// ---------------- launcher ----------------
extern "C" void kernel_launch(void* const* d_in, const int* in_sizes, int n_in,
                              void* d_out, int out_size) {
    const float* x     = (const float*)d_in[0];
    const float* cond  = (const float*)d_in[1];
    const int*   resid = (const int*)d_in[2];
    const float* W1    = (const float*)d_in[3];
    const float* b1    = (const float*)d_in[4];
    const float* gamma = (const float*)d_in[5];
    const float* beta  = (const float*)d_in[6];
    const float* W2    = (const float*)d_in[7];
    const float* b2    = (const float*)d_in[8];
    float* out = (float*)d_out;

    (void)in_sizes; (void)n_in; (void)out_size;

    k_pool<<<RR, 256>>>((const float4*)x, resid);
    k_fused<<<NB, 128>>>(cond, W1, b1, gamma, beta, W2, b2, out);
}

// round 10
// speedup vs baseline: 1.1290x; 1.1290x over previous
#include <cuda_runtime.h>

#define BB 8
#define NN 20000
#define DD 640
#define RR 2500
#define BINS 10
#define HID 128
#define EPSV 1e-5f
#define NB 592              // persistent grid: 4 blocks/SM on 148 SMs
#define NWARPS (NB * 4)
#define POOL_BLOCKS ((BB * NN) / 8)          // 20000 pool blocks (8 warps each)
#define OFF_BLOCKS ((NN + 255) / 256)        // 79 tail blocks compute g_off

typedef unsigned long long ull;

// ---------------- scratch (zero-init at load; self-restoring per run) --------
__device__ float g_pooled[RR * BB * BINS];   // [r][b][bin]; re-zeroed in phase 1
__device__ ull   g_a2[RR * 2 * BB * 32];     // packed pre-activations (overwritten)
__device__ int   g_off[RR + 1];              // segment offsets (res_id sorted)
__device__ float g_sum[HID];
__device__ float g_sumsq[HID];
__device__ unsigned int g_done;              // phase-1 barrier
__device__ unsigned int g_done2;             // end counter (no spinners)

// ---------------- packed f32x2 helpers (sm_100+) ----------------
__device__ __forceinline__ ull pk2(float lo, float hi) {
    ull r; asm("mov.b64 %0,{%1,%2};" : "=l"(r) : "f"(lo), "f"(hi)); return r;
}
__device__ __forceinline__ void upk2(ull v, float& lo, float& hi) {
    asm("mov.b64 {%0,%1},%2;" : "=f"(lo), "=f"(hi) : "l"(v));
}
__device__ __forceinline__ ull add2(ull a, ull b) {
    ull d; asm("add.rn.f32x2 %0,%1,%2;" : "=l"(d) : "l"(a), "l"(b)); return d;
}
__device__ __forceinline__ ull mul2(ull a, ull b) {
    ull d; asm("mul.rn.f32x2 %0,%1,%2;" : "=l"(d) : "l"(a), "l"(b)); return d;
}
__device__ __forceinline__ ull fma2(ull a, ull b, ull c) {
    ull d; asm("fma.rn.f32x2 %0,%1,%2,%3;" : "=l"(d) : "l"(a), "l"(b), "l"(c)); return d;
}
__device__ __forceinline__ ull relu2(ull a) {
    float lo, hi; upk2(a, lo, hi);
    return pk2(fmaxf(lo, 0.0f), fmaxf(hi, 0.0f));
}

// ---------------- K1: pooling (R7 form: max-MLP) + offsets tail --------------
// Pool blocks: one warp per (b, atom) row, 160 float4, coalesced streaming,
// 10 spread atomics/row. Tail blocks: boundary-detect offsets from res_id.
__global__ void k_pool(const float4* __restrict__ x4, const int* __restrict__ res_id) {
    int tail = blockIdx.x - POOL_BLOCKS;
    if (tail >= 0) {
        int i = tail * 256 + threadIdx.x;
        if (i < NN) {
            int r = res_id[i];
            if (i == 0 || res_id[i - 1] != r) g_off[r] = i;
        }
        if (i == 0) g_off[RR] = NN;
        return;
    }

    int w = (blockIdx.x * blockDim.x + threadIdx.x) >> 5;
    int lane = threadIdx.x & 31;
    int b = w / NN;
    int n = w - b * NN;
    int rid = res_id[n];
    const float4* row = x4 + (size_t)w * (DD / 4);

    float s[5];
#pragma unroll
    for (int k = 0; k < 5; k++) {
        float4 v = __ldcs(&row[lane + 32 * k]);   // read-once: evict-first
        s[k] = (v.x + v.y) + (v.z + v.w);
    }
#pragma unroll
    for (int k = 0; k < 5; k++) {
#pragma unroll
        for (int off = 8; off >= 1; off >>= 1)
            s[k] += __shfl_down_sync(0xffffffffu, s[k], off, 16);
    }
    if ((lane & 15) == 0) {
        int half = lane >> 4;
        float* dst = &g_pooled[((size_t)rid * BB + b) * BINS];
#pragma unroll
        for (int k = 0; k < 5; k++)
            atomicAdd(&dst[2 * k + half], s[k]);
    }
}

// ---------------- K2: persistent fused stats + fold + output -----------------
__global__ void __launch_bounds__(128, 4) k_fused(
        const float* __restrict__ cond, const float* __restrict__ W1,
        const float* __restrict__ b1, const float* __restrict__ gamma,
        const float* __restrict__ beta, const float* __restrict__ W2,
        const float* __restrict__ b2, float* __restrict__ out) {
    __shared__ ull s_w1p[BINS][2][32];   // packed pooled-part of W1 (5KB)
    __shared__ float ssum[HID];
    __shared__ float ssq[HID];
    __shared__ bool s_last;
    int t = threadIdx.x, lane = t & 31;

    // cooperative pack of W1[0:10] into smem
    for (int e = t; e < BINS * 64; e += 128) {
        int j = e >> 6, k2 = (e >> 5) & 1, l = e & 31;
        int f = l + 64 * k2;
        s_w1p[j][k2][l] = pk2(__ldg(&W1[j * HID + f]), __ldg(&W1[j * HID + f + 32]));
    }
    ssum[t] = 0.0f; ssq[t] = 0.0f;

    // conditioner part + bias in registers (feature pairing (f, f+32))
    ull w1c2[3][2], bb2[2];
#pragma unroll
    for (int j = 0; j < 3; j++) {
        w1c2[j][0] = pk2(__ldg(&W1[(BINS + j) * HID + lane]), __ldg(&W1[(BINS + j) * HID + lane + 32]));
        w1c2[j][1] = pk2(__ldg(&W1[(BINS + j) * HID + lane + 64]), __ldg(&W1[(BINS + j) * HID + lane + 96]));
    }
    bb2[0] = pk2(__ldg(&b1[lane]), __ldg(&b1[lane + 32]));
    bb2[1] = pk2(__ldg(&b1[lane + 64]), __ldg(&b1[lane + 96]));
    __syncthreads();

    int warp0 = (blockIdx.x * blockDim.x + t) >> 5;

    // ===== phase 1: one FULL residue per warp ================================
    // Compute a2 from pooled, zero the pooled row (unique reader -> race-free),
    // store a2 for phase 2, accumulate stats over all cnt atoms (<=10).
    ull ls2[2] = {0, 0}, lq2[2] = {0, 0};
    for (int r = warp0; r < RR; r += NWARPS) {
        int o0 = g_off[r], o1 = g_off[r + 1], cnt = o1 - o0;
        float inv = 1.0f / ((float)cnt * 64.0f);
        float* pp = &g_pooled[(size_t)r * BB * BINS];
        float p0 = pp[lane], p1 = pp[lane + 32], p2 = (lane < 16) ? pp[lane + 64] : 0.0f;

        ull a2[BB][2];
#pragma unroll
        for (int b = 0; b < BB; b++) { a2[b][0] = bb2[0]; a2[b][1] = bb2[1]; }
#pragma unroll
        for (int j = 0; j < BINS; j++) {
            ull wj0 = s_w1p[j][0][lane], wj1 = s_w1p[j][1][lane];
#pragma unroll
            for (int b = 0; b < BB; b++) {
                int idx = b * BINS + j;
                float v = __shfl_sync(0xffffffffu, idx < 32 ? p0 : (idx < 64 ? p1 : p2), idx & 31);
                float pm = v * inv;
                ull pm2 = pk2(pm, pm);
                a2[b][0] = fma2(pm2, wj0, a2[b][0]);
                a2[b][1] = fma2(pm2, wj1, a2[b][1]);
            }
        }
        // restore zeros for next replay's atomic pooling
        pp[lane] = 0.0f; pp[lane + 32] = 0.0f;
        if (lane < 16) pp[lane + 64] = 0.0f;
        // publish a2 for phase 2 (coalesced 256B rows)
#pragma unroll
        for (int k2 = 0; k2 < 2; k2++)
#pragma unroll
            for (int b = 0; b < BB; b++)
                g_a2[(((size_t)r * 2 + k2) * BB + b) * 32 + lane] = a2[b][k2];

        float cseg = (lane < 3 * cnt) ? __ldg(&cond[o0 * 3 + lane]) : 0.0f;
        for (int i = 0; i < cnt; i++) {
            float c0 = __shfl_sync(0xffffffffu, cseg, 3 * i);
            float c1 = __shfl_sync(0xffffffffu, cseg, 3 * i + 1);
            float c2 = __shfl_sync(0xffffffffu, cseg, 3 * i + 2);
            ull c02 = pk2(c0, c0), c12 = pk2(c1, c1), c22 = pk2(c2, c2);
#pragma unroll
            for (int k2 = 0; k2 < 2; k2++) {
                ull cc = fma2(c02, w1c2[0][k2], fma2(c12, w1c2[1][k2], mul2(c22, w1c2[2][k2])));
#pragma unroll
                for (int b = 0; b < BB; b++) {
                    ull v = relu2(add2(a2[b][k2], cc));
                    ls2[k2] = add2(ls2[k2], v);
                    lq2[k2] = fma2(v, v, lq2[k2]);
                }
            }
        }
    }
    {
        float x0, x1;
        upk2(ls2[0], x0, x1); atomicAdd(&ssum[lane], x0); atomicAdd(&ssum[lane + 32], x1);
        upk2(ls2[1], x0, x1); atomicAdd(&ssum[lane + 64], x0); atomicAdd(&ssum[lane + 96], x1);
        upk2(lq2[0], x0, x1); atomicAdd(&ssq[lane], x0);  atomicAdd(&ssq[lane + 32], x1);
        upk2(lq2[1], x0, x1); atomicAdd(&ssq[lane + 64], x0); atomicAdd(&ssq[lane + 96], x1);
    }
    __syncthreads();
    atomicAdd(&g_sum[t], ssum[t]);
    atomicAdd(&g_sumsq[t], ssq[t]);
    __syncthreads();

    // ===== phase barrier (all 592 blocks resident by __launch_bounds__) ======
    __threadfence();
    if (t == 0) {
        atomicAdd(&g_done, 1u);
        while (atomicAdd(&g_done, 0u) < (unsigned)gridDim.x) __nanosleep(64);
    }
    __syncthreads();
    __threadfence();

    // ===== per-warp layernorm fold ===========================================
    ull w22[2][3];
    float bo0, bo1, bo2;
    {
        const float invn = 1.0f / (float)(BB * NN);
        float w2s[4][3];
        float offc[3] = {0, 0, 0};
#pragma unroll
        for (int k = 0; k < 4; k++) {
            int f = lane + 32 * k;
            float mu = g_sum[f] * invn;
            float var = g_sumsq[f] * invn - mu * mu;
            float s = rsqrtf(var + EPSV) * __ldg(&gamma[f]);
            float off = __ldg(&beta[f]) - mu * s;
#pragma unroll
            for (int j = 0; j < 3; j++) {
                float w = __ldg(&W2[f * 3 + j]);
                w2s[k][j] = w * s;
                offc[j] += off * w;
            }
        }
#pragma unroll
        for (int o = 16; o >= 1; o >>= 1) {
            offc[0] += __shfl_xor_sync(0xffffffffu, offc[0], o);
            offc[1] += __shfl_xor_sync(0xffffffffu, offc[1], o);
            offc[2] += __shfl_xor_sync(0xffffffffu, offc[2], o);
        }
        bo0 = offc[0] + __ldg(&b2[0]);
        bo1 = offc[1] + __ldg(&b2[1]);
        bo2 = offc[2] + __ldg(&b2[2]);
#pragma unroll
        for (int j = 0; j < 3; j++) {
            w22[0][j] = pk2(w2s[0][j], w2s[1][j]);
            w22[1][j] = pk2(w2s[2][j], w2s[3][j]);
        }
    }

    // ===== phase 2: output; a2 LOADED (no recompute, no pooled access) =======
    for (int task = warp0; task < 2 * RR; task += NWARPS) {
        int r = task >> 1, half = task & 1;
        int o0 = g_off[r], o1 = g_off[r + 1], cnt = o1 - o0;
        int lo = o0 + ((cnt * half) >> 1), hi = o0 + ((cnt * (half + 1)) >> 1);
        int subcnt = hi - lo;

        ull a2[BB][2];
#pragma unroll
        for (int k2 = 0; k2 < 2; k2++)
#pragma unroll
            for (int b = 0; b < BB; b++)
                a2[b][k2] = g_a2[(((size_t)r * 2 + k2) * BB + b) * 32 + lane];

        float cseg = (lane < 3 * subcnt) ? __ldg(&cond[lo * 3 + lane]) : 0.0f;

        for (int i = 0; i < subcnt; i++) {
            float c0 = __shfl_sync(0xffffffffu, cseg, 3 * i);
            float c1 = __shfl_sync(0xffffffffu, cseg, 3 * i + 1);
            float c2 = __shfl_sync(0xffffffffu, cseg, 3 * i + 2);
            ull c02 = pk2(c0, c0), c12 = pk2(c1, c1), c22 = pk2(c2, c2);
            ull cc[2];
#pragma unroll
            for (int k2 = 0; k2 < 2; k2++)
                cc[k2] = fma2(c02, w1c2[0][k2], fma2(c12, w1c2[1][k2], mul2(c22, w1c2[2][k2])));

#pragma unroll
            for (int g = 0; g < 2; g++) {
                ull y01[4];
                ull y2p[2];
#pragma unroll
                for (int q = 0; q < 4; q++) {
                    int b = g * 4 + q;
                    ull s0 = 0, s1 = 0, s2 = 0;
#pragma unroll
                    for (int k2 = 0; k2 < 2; k2++) {
                        ull v = relu2(add2(a2[b][k2], cc[k2]));
                        s0 = fma2(v, w22[k2][0], s0);
                        s1 = fma2(v, w22[k2][1], s1);
                        s2 = fma2(v, w22[k2][2], s2);
                    }
                    float u0, u1, r0, r1, r2;
                    upk2(s0, u0, u1); r0 = u0 + u1;
                    upk2(s1, u0, u1); r1 = u0 + u1;
                    upk2(s2, u0, u1); r2 = u0 + u1;
                    y01[q] = pk2(r0, r1);
                    if (q & 1) {
                        float plo, phi; upk2(y2p[q >> 1], plo, phi);
                        y2p[q >> 1] = pk2(plo, r2);
                    } else {
                        y2p[q >> 1] = pk2(r2, 0.0f);
                    }
                }
#pragma unroll
                for (int o = 16; o >= 1; o >>= 1) {
#pragma unroll
                    for (int q = 0; q < 4; q++)
                        y01[q] = add2(y01[q], __shfl_down_sync(0xffffffffu, y01[q], o));
#pragma unroll
                    for (int q = 0; q < 2; q++)
                        y2p[q] = add2(y2p[q], __shfl_down_sync(0xffffffffu, y2p[q], o));
                }
                if (lane == 0) {
#pragma unroll
                    for (int q = 0; q < 4; q++) {
                        int b = g * 4 + q;
                        float r0, r1, r2, rlo, rhi;
                        upk2(y01[q], r0, r1);
                        upk2(y2p[q >> 1], rlo, rhi);
                        r2 = (q & 1) ? rhi : rlo;
                        float* p = out + ((size_t)b * NN + (lo + i)) * 3;
                        p[0] = r0 + bo0;
                        p[1] = r1 + bo1;
                        p[2] = r2 + bo2;
                    }
                }
            }
        }
    }

    // ===== cleanup: last block resets tiny state (no spin) ===================
    __syncthreads();
    __threadfence();
    if (t == 0) s_last = (atomicAdd(&g_done2, 1u) == (unsigned)gridDim.x - 1);
    __syncthreads();
    if (s_last) {
        g_sum[t] = 0.0f;
        g_sumsq[t] = 0.0f;
        __syncthreads();
        __threadfence();
        if (t == 0) { g_done = 0; g_done2 = 0; }
    }
}

// ---------------- launcher ----------------
extern "C" void kernel_launch(void* const* d_in, const int* in_sizes, int n_in,
                              void* d_out, int out_size) {
    const float* x     = (const float*)d_in[0];
    const float* cond  = (const float*)d_in[1];
    const int*   resid = (const int*)d_in[2];
    const float* W1    = (const float*)d_in[3];
    const float* b1    = (const float*)d_in[4];
    const float* gamma = (const float*)d_in[5];
    const float* beta  = (const float*)d_in[6];
    const float* W2    = (const float*)d_in[7];
    const float* b2    = (const float*)d_in[8];
    float* out = (float*)d_out;

    (void)in_sizes; (void)n_in; (void)out_size;

    k_pool<<<POOL_BLOCKS + OFF_BLOCKS, 256>>>((const float4*)x, resid);
    k_fused<<<NB, 128>>>(cond, W1, b1, gamma, beta, W2, b2, out);
}